// round 15
// baseline (speedup 1.0000x reference)
#include <cuda_runtime.h>
#include <cuda_fp16.h>
#include <math.h>
#include <stdint.h>

#define N_ROWS  131072
#define S_DIM   64
#define H_DIM   128
#define K_CODES 512
#define A_DIM   8
#define TM      128
#define NTHREADS 512
#define MARGIN  0.05f

typedef uint32_t u32;

// ===================== warp-level tensor ops (base PTX) =====================
#define LDSM4(r, addr)                                                        \
    asm volatile("ldmatrix.sync.aligned.m8n8.x4.shared.b16 {%0,%1,%2,%3}, [%4];" \
                 : "=r"((r)[0]), "=r"((r)[1]), "=r"((r)[2]), "=r"((r)[3])     \
                 : "r"(addr))

__device__ __forceinline__ void mma16816(float* c, const u32* a, u32 b0, u32 b1) {
    asm volatile("mma.sync.aligned.m16n8k16.row.col.f32.f16.f16.f32 "
                 "{%0,%1,%2,%3}, {%4,%5,%6,%7}, {%8,%9}, {%0,%1,%2,%3};"
                 : "+f"(c[0]), "+f"(c[1]), "+f"(c[2]), "+f"(c[3])
                 : "r"(a[0]), "r"(a[1]), "r"(a[2]), "r"(a[3]), "r"(b0), "r"(b1));
}

__device__ __forceinline__ u32 smem_u32(const void* p) {
    u32 a; asm("{ .reg .u64 t; cvta.to.shared.u64 t, %1; cvt.u32.u64 %0, t; }"
               : "=r"(a) : "l"(p)); return a;
}
__device__ __forceinline__ u32 pkh(float a, float b) {
    __half2 t; t.x = __float2half_rn(a); t.y = __float2half_rn(b);
    return *reinterpret_cast<u32*>(&t);
}
__device__ __forceinline__ void cpa16(u32 dst, const void* src) {
    asm volatile("cp.async.cg.shared.global [%0], [%1], 16;"
                 :: "r"(dst), "l"(src) : "memory");
}
#define CP_COMMIT() asm volatile("cp.async.commit_group;" ::: "memory")
#define CP_WAIT(n)  asm volatile("cp.async.wait_group %0;" :: "n"(n) : "memory")

// branchless top-3 insert of packed key (float-bits masked | code), ascending
__device__ __forceinline__ void key3(u32 k, u32* t) {
    u32 a = umin(t[0], k);
    u32 b = umax(t[0], k);
    t[0] = a;
    u32 c = umin(t[1], b);
    u32 d = umax(t[1], b);
    t[1] = c;
    t[2] = umin(t[2], d);
}

// ===================== device globals =====================
__device__ float g_ee[K_CODES];
__device__ float g_probs[K_CODES * A_DIM];
__device__ float g_value[K_CODES];

// fp16 images:  W1T hi/lo (pitch 72), WhT hi/lo (pitch 136), E hi-only (4 x [128][136])
#define IMG_W1 0
#define IMG_WH 18432
#define IMG_E  53248
__device__ __half g_img[122880];

// ===================== kernel 1: merged prelim =====================
__global__ void prep_all(const float* __restrict__ emb,
                         const float* __restrict__ Wa, const float* __restrict__ ba,
                         const float* __restrict__ Wv, const float* __restrict__ bv,
                         const float* __restrict__ W1, const float* __restrict__ Wh)
{
    if (blockIdx.x < 64) {
        int code = blockIdx.x * 8 + (threadIdx.x >> 5);
        int lane = threadIdx.x & 31;
        const float* e = emb + code * H_DIM;
        double ee = 0.0;
        float logit[A_DIM];
#pragma unroll
        for (int a = 0; a < A_DIM; a++) logit[a] = 0.0f;
        float val = 0.0f;
#pragma unroll
        for (int j = 0; j < 4; j++) {
            int d = lane + 32 * j;
            float ej = e[d];
            ee += (double)ej * (double)ej;
#pragma unroll
            for (int a = 0; a < A_DIM; a++) logit[a] = fmaf(ej, Wa[d * A_DIM + a], logit[a]);
            val = fmaf(ej, Wv[d], val);
        }
#pragma unroll
        for (int off = 16; off; off >>= 1) {
            ee  += __shfl_xor_sync(0xFFFFFFFFu, ee,  off);
            val += __shfl_xor_sync(0xFFFFFFFFu, val, off);
#pragma unroll
            for (int a = 0; a < A_DIM; a++)
                logit[a] += __shfl_xor_sync(0xFFFFFFFFu, logit[a], off);
        }
        if (lane == 0) {
#pragma unroll
            for (int a = 0; a < A_DIM; a++) logit[a] += ba[a];
            g_ee[code] = (float)ee;
            g_value[code] = val + bv[0];
            float m = logit[0];
#pragma unroll
            for (int a = 1; a < A_DIM; a++) m = fmaxf(m, logit[a]);
            float p[A_DIM], s = 0.0f;
#pragma unroll
            for (int a = 0; a < A_DIM; a++) { p[a] = expf(logit[a] - m); s += p[a]; }
#pragma unroll
            for (int a = 0; a < A_DIM; a++) g_probs[code * A_DIM + a] = p[a] / s;
        }
        return;
    }
    int idx = (blockIdx.x - 64) * 256 + threadIdx.x;
    if (idx < 8192) {                       // W1T hi/lo
        int n = idx >> 6, s = idx & 63;
        float v = W1[s * H_DIM + n];
        __half h = __float2half_rn(v);
        __half l = __float2half_rn(v - __half2float(h));
        int o = n * 72 + s;
        g_img[IMG_W1 + o] = h;
        g_img[IMG_W1 + 9216 + o] = l;
    } else if (idx < 24576) {               // WhT hi/lo
        int j = idx - 8192;
        int n = j >> 7, k = j & 127;
        float v = Wh[k * H_DIM + n];
        __half h = __float2half_rn(v);
        __half l = __float2half_rn(v - __half2float(h));
        int o = n * 136 + k;
        g_img[IMG_WH + o] = h;
        g_img[IMG_WH + 17408 + o] = l;
    } else if (idx < 90112) {               // E hi only
        int j = idx - 24576;
        int g = j >> 7, d = j & 127;
        int t = g >> 7, c = g & 127;
        g_img[IMG_E + t * 17408 + c * 136 + d] = __float2half_rn(emb[g * H_DIM + d]);
    }
}

// ===================== kernel 2: fused main =====================
#define OFF_B1   0        // float[128]
#define OFF_BH   512
#define OFF_VV   1024     // float[128][2]
#define OFF_EE   2048     // float[512]
#define OFF_KEY  4096     // u32[128][6] = 3072 B
#define REG_A    7168     // input hi|lo(+18432) p144; W1 hi(+36864)|lo(+55296); later x2 hi|lo(+34816) p272
#define REG_C    80896    // x1 hi|lo(+34816) p272; later E hi tiles 0(+0),1(+34816)
#define REG_D    150528   // Wh hi|lo(+34816) p272; later E hi tiles 2(+0),3(+34816)
#define SMEM_BYTES 220160

// 3-pass split GEMM, warp tile 16x64 (encoder)
template<int KS>
__device__ __forceinline__ void run_gemm4(u32 aH, u32 aL, u32 bH, u32 bL,
                                          int pitchA, int pitchB,
                                          int lane, int wrow, int cbase, float (*acc)[4])
{
    const u32 aoff = (u32)(wrow + (lane & 15)) * pitchA + (u32)(lane >> 4) * 16;
    const u32 boff = (u32)(cbase + (lane & 7) + ((lane >> 4) << 3)) * pitchB
                   + (u32)((lane >> 3) & 1) * 16;
#pragma unroll
    for (int ks = 0; ks < KS; ks++) {
        u32 ah[4], al[4];
        LDSM4(ah, aH + aoff + ks * 32);
        LDSM4(al, aL + aoff + ks * 32);
#pragma unroll
        for (int half = 0; half < 2; half++) {
            const u32 base = boff + (u32)(half * 2) * 16 * pitchB + ks * 32;
            u32 bh0[4], bh1[4], bl0[4], bl1[4];
            LDSM4(bh0, bH + base);
            LDSM4(bh1, bH + base + 16u * pitchB);
            float* a0 = acc[half * 4 + 0];
            float* a1 = acc[half * 4 + 1];
            float* a2 = acc[half * 4 + 2];
            float* a3 = acc[half * 4 + 3];
            mma16816(a0, ah, bh0[0], bh0[1]);
            mma16816(a1, ah, bh0[2], bh0[3]);
            mma16816(a2, ah, bh1[0], bh1[1]);
            mma16816(a3, ah, bh1[2], bh1[3]);
            mma16816(a0, al, bh0[0], bh0[1]);
            mma16816(a1, al, bh0[2], bh0[3]);
            mma16816(a2, al, bh1[0], bh1[1]);
            mma16816(a3, al, bh1[2], bh1[3]);
            LDSM4(bl0, bL + base);
            LDSM4(bl1, bL + base + 16u * pitchB);
            mma16816(a0, ah, bl0[0], bl0[1]);
            mma16816(a1, ah, bl0[2], bl0[3]);
            mma16816(a2, ah, bl1[0], bl1[1]);
            mma16816(a3, ah, bl1[2], bl1[3]);
        }
    }
}

// hi-only score GEMM, warp tile 16x64, A from smem
__device__ __forceinline__ void run_gemm_hi(u32 aH, u32 bH,
                                            int pitchA, int pitchB,
                                            int lane, int wrow, int cbase, float (*acc)[4])
{
    const u32 aoff = (u32)(wrow + (lane & 15)) * pitchA + (u32)(lane >> 4) * 16;
    const u32 boff = (u32)(cbase + (lane & 7) + ((lane >> 4) << 3)) * pitchB
                   + (u32)((lane >> 3) & 1) * 16;
#pragma unroll
    for (int ks = 0; ks < 8; ks++) {
        u32 ah[4];
        LDSM4(ah, aH + aoff + ks * 32);
#pragma unroll
        for (int bt = 0; bt < 4; bt++) {
            u32 bh[4];
            LDSM4(bh, bH + boff + (u32)bt * 16 * pitchB + ks * 32);
            mma16816(acc[2 * bt],     ah, bh[0], bh[1]);
            mma16816(acc[2 * bt + 1], ah, bh[2], bh[3]);
        }
    }
}

__global__ __launch_bounds__(NTHREADS, 1)
void fused_kernel(const float* __restrict__ in,
                  const float* __restrict__ b1, const float* __restrict__ bh,
                  const float* __restrict__ emb,
                  float* __restrict__ out)
{
    extern __shared__ __align__(16) unsigned char smem[];
    const u32 sb = smem_u32(smem);
    char* sc = (char*)smem;

    const int tid   = threadIdx.x;
    const int wid   = tid >> 5;
    const int lane  = tid & 31;
    const int g     = lane >> 2;
    const int q     = lane & 3;
    const int wrow  = (wid & 7) * 16;      // row strip
    const int chalf = wid >> 3;            // column half
    const int cbase = chalf * 64;
    const int r1 = wrow + g, r2 = r1 + 8;
    const int rowBase = blockIdx.x * TM;

    float* sB1  = (float*)(sc + OFF_B1);
    float* sBH  = (float*)(sc + OFF_BH);
    float* sVV  = (float*)(sc + OFF_VV);
    float* sEE  = (float*)(sc + OFF_EE);
    u32*   sKEY = (u32*)  (sc + OFF_KEY);

    const char* gimg = (const char*)g_img;

    // ---------------- Stage 0: prefetch W1, Wh; split input ----------------
    for (int i = tid; i < 2304; i += NTHREADS)
        cpa16(sb + REG_A + 36864 + i * 16, gimg + IMG_W1 * 2 + i * 16);
    CP_COMMIT();
    for (int i = tid; i < 4352; i += NTHREADS)
        cpa16(sb + REG_D + i * 16, gimg + IMG_WH * 2 + i * 16);
    CP_COMMIT();

    for (int p = tid; p < 128 * 32; p += NTHREADS) {
        int row = p >> 5, pc = p & 31;
        float2 v = *(const float2*)(in + (size_t)(rowBase + row) * S_DIM + 2 * pc);
        __half h0 = __float2half_rn(v.x);
        __half h1 = __float2half_rn(v.y);
        u32 o = (u32)row * 144 + (u32)pc * 4;
        *(u32*)(sc + REG_A + o)         = pkh(__half2float(h0), __half2float(h1));
        *(u32*)(sc + REG_A + 18432 + o) = pkh(v.x - __half2float(h0), v.y - __half2float(h1));
    }
    if (tid < 128) { sB1[tid] = b1[tid]; sBH[tid] = bh[tid]; }
    if (tid < 512) sEE[tid] = g_ee[tid];
    CP_WAIT(1);
    __syncthreads();

    float accA[8][4];

    // ---------------- Stage 1: x1 = relu(in @ W1 + b1) ----------------
#pragma unroll
    for (int t = 0; t < 8; t++)
#pragma unroll
        for (int j = 0; j < 4; j++) accA[t][j] = 0.0f;
    run_gemm4<4>(sb + REG_A, sb + REG_A + 18432,
                 sb + REG_A + 36864, sb + REG_A + 55296, 144, 144, lane, wrow, cbase, accA);
#pragma unroll
    for (int t = 0; t < 8; t++) {
        int c = cbase + 8 * t + 2 * q;
        float z0 = fmaxf(accA[t][0] + sB1[c],     0.0f);
        float z1 = fmaxf(accA[t][1] + sB1[c + 1], 0.0f);
        float z2 = fmaxf(accA[t][2] + sB1[c],     0.0f);
        float z3 = fmaxf(accA[t][3] + sB1[c + 1], 0.0f);
        __half h0 = __float2half_rn(z0), h1 = __float2half_rn(z1);
        __half h2 = __float2half_rn(z2), h3 = __float2half_rn(z3);
        u32 o1 = (u32)r1 * 272 + (u32)c * 2;
        u32 o2 = (u32)r2 * 272 + (u32)c * 2;
        *(u32*)(sc + REG_C + o1)         = pkh(__half2float(h0), __half2float(h1));
        *(u32*)(sc + REG_C + o2)         = pkh(__half2float(h2), __half2float(h3));
        *(u32*)(sc + REG_C + 34816 + o1) = pkh(z0 - __half2float(h0), z1 - __half2float(h1));
        *(u32*)(sc + REG_C + 34816 + o2) = pkh(z2 - __half2float(h2), z3 - __half2float(h3));
    }
    CP_WAIT(0);
    __syncthreads();

    // ---------------- Stage 2: x2 = relu(x1 @ Wh + bh) ----------------
#pragma unroll
    for (int t = 0; t < 8; t++)
#pragma unroll
        for (int j = 0; j < 4; j++) accA[t][j] = 0.0f;
    run_gemm4<8>(sb + REG_C, sb + REG_C + 34816,
                 sb + REG_D, sb + REG_D + 34816, 272, 272, lane, wrow, cbase, accA);
    __syncthreads();   // MMA reads of REG_C/REG_D complete

    // prefetch all 4 E hi tiles: 0,1 -> REG_C; 2,3 -> REG_D
#pragma unroll
    for (int t4 = 0; t4 < 4; t4++) {
        u32 dst = ((t4 < 2) ? (sb + REG_C) : (sb + REG_D)) + (u32)(t4 & 1) * 34816;
        const char* src = gimg + (IMG_E + t4 * 17408) * 2;
        for (int i = tid; i < 2176; i += NTHREADS)
            cpa16(dst + i * 16, src + i * 16);
    }
    CP_COMMIT();

    // stage 2 epilogue part 1 (overlaps fills): hi image + vv only.
    // accA stays LIVE: lo image is produced after the sync, under tile-0 GEMM.
    {
        float vp1 = 0.0f, vp2 = 0.0f;
#pragma unroll
        for (int t = 0; t < 8; t++) {
            int c = cbase + 8 * t + 2 * q;
            float z0 = fmaxf(accA[t][0] + sBH[c],     0.0f);
            float z1 = fmaxf(accA[t][1] + sBH[c + 1], 0.0f);
            float z2 = fmaxf(accA[t][2] + sBH[c],     0.0f);
            float z3 = fmaxf(accA[t][3] + sBH[c + 1], 0.0f);
            __half h0 = __float2half_rn(z0), h1 = __float2half_rn(z1);
            __half h2 = __float2half_rn(z2), h3 = __float2half_rn(z3);
            float fl0 = z0 - __half2float(h0), fl1 = z1 - __half2float(h1);
            float fl2 = z2 - __half2float(h2), fl3 = z3 - __half2float(h3);
            float x0 = __half2float(h0) + __half2float(__float2half_rn(fl0));
            float x1 = __half2float(h1) + __half2float(__float2half_rn(fl1));
            float x2 = __half2float(h2) + __half2float(__float2half_rn(fl2));
            float x3 = __half2float(h3) + __half2float(__float2half_rn(fl3));
            vp1 = fmaf(x0, x0, vp1); vp1 = fmaf(x1, x1, vp1);
            vp2 = fmaf(x2, x2, vp2); vp2 = fmaf(x3, x3, vp2);
            u32 o1 = (u32)r1 * 272 + (u32)c * 2;
            u32 o2 = (u32)r2 * 272 + (u32)c * 2;
            *(u32*)(sc + REG_A + o1) = pkh(__half2float(h0), __half2float(h1));
            *(u32*)(sc + REG_A + o2) = pkh(__half2float(h2), __half2float(h3));
        }
        vp1 += __shfl_xor_sync(0xFFFFFFFFu, vp1, 1);
        vp1 += __shfl_xor_sync(0xFFFFFFFFu, vp1, 2);
        vp2 += __shfl_xor_sync(0xFFFFFFFFu, vp2, 1);
        vp2 += __shfl_xor_sync(0xFFFFFFFFu, vp2, 2);
        if (q == 0) { sVV[r1 * 2 + chalf] = vp1; sVV[r2 * 2 + chalf] = vp2; }
    }
    CP_WAIT(0);
    __syncthreads();   // x2 HI image + vv + ALL E tiles ready

    // ---------------- Score: ping-pong; lo-epilogue hides under tile 0 -------
    u32 k1[3] = {0xFFFFFFFFu, 0xFFFFFFFFu, 0xFFFFFFFFu};
    u32 k2[3] = {0xFFFFFFFFu, 0xFFFFFFFFu, 0xFFFFFFFFu};
    float accB[8][4];

#define TILE_BUF(T) ((((T) < 2) ? (sb + REG_C) : (sb + REG_D)) + (u32)((T) & 1) * 34816)

#define ZERO_ACC(A)                                                           \
    do {                                                                      \
        _Pragma("unroll")                                                     \
        for (int t = 0; t < 8; t++)                                           \
            _Pragma("unroll")                                                 \
            for (int j = 0; j < 4; j++) (A)[t][j] = 0.0f;                     \
    } while (0)

#define SELECT(A, T)                                                          \
    do {                                                                      \
        int codeBase = (T) * 128 + cbase;                                     \
        _Pragma("unroll")                                                     \
        for (int t = 0; t < 8; t++) {                                         \
            int c = codeBase + 8 * t + 2 * q;                                 \
            _Pragma("unroll")                                                 \
            for (int jj = 0; jj < 2; jj++) {                                  \
                int code = c + jj;                                            \
                float ee = sEE[code];                                         \
                float da = fmaf(-2.0f, (A)[t][jj],     vva) + ee;             \
                float db = fmaf(-2.0f, (A)[t][2 + jj], vvb) + ee;             \
                key3((__float_as_uint(da) & 0xFFFFFE00u) | (u32)code, k1);    \
                key3((__float_as_uint(db) & 0xFFFFFE00u) | (u32)code, k2);    \
            }                                                                 \
        }                                                                     \
    } while (0)

    ZERO_ACC(accB);
    run_gemm_hi(sb + REG_A, TILE_BUF(0), 272, 272, lane, wrow, cbase, accB);

    // epilogue part 2: lo image from still-live accA (overlaps tile-0 GEMM)
#pragma unroll
    for (int t = 0; t < 8; t++) {
        int c = cbase + 8 * t + 2 * q;
        float z0 = fmaxf(accA[t][0] + sBH[c],     0.0f);
        float z1 = fmaxf(accA[t][1] + sBH[c + 1], 0.0f);
        float z2 = fmaxf(accA[t][2] + sBH[c],     0.0f);
        float z3 = fmaxf(accA[t][3] + sBH[c + 1], 0.0f);
        float fl0 = z0 - __half2float(__float2half_rn(z0));
        float fl1 = z1 - __half2float(__float2half_rn(z1));
        float fl2 = z2 - __half2float(__float2half_rn(z2));
        float fl3 = z3 - __half2float(__float2half_rn(z3));
        u32 o1 = (u32)r1 * 272 + (u32)c * 2;
        u32 o2 = (u32)r2 * 272 + (u32)c * 2;
        *(u32*)(sc + REG_A + 34816 + o1) = pkh(fl0, fl1);
        *(u32*)(sc + REG_A + 34816 + o2) = pkh(fl2, fl3);
    }
    const float vva = sVV[r1 * 2] + sVV[r1 * 2 + 1];
    const float vvb = sVV[r2 * 2] + sVV[r2 * 2 + 1];

    ZERO_ACC(accA);
    run_gemm_hi(sb + REG_A, TILE_BUF(1), 272, 272, lane, wrow, cbase, accA);
    SELECT(accB, 0);
    ZERO_ACC(accB);
    run_gemm_hi(sb + REG_A, TILE_BUF(2), 272, 272, lane, wrow, cbase, accB);
    SELECT(accA, 1);
    ZERO_ACC(accA);
    run_gemm_hi(sb + REG_A, TILE_BUF(3), 272, 272, lane, wrow, cbase, accA);
    SELECT(accB, 2);
    SELECT(accA, 3);

    // merge top-3 across the 4 q lanes of each row half
#pragma unroll
    for (int mk = 1; mk <= 2; mk <<= 1) {
#pragma unroll
        for (int k = 0; k < 3; k++) {
            u32 o1 = __shfl_xor_sync(0xFFFFFFFFu, k1[k], mk);
            u32 o2 = __shfl_xor_sync(0xFFFFFFFFu, k2[k], mk);
            key3(o1, k1);
            key3(o2, k2);
        }
    }
    if (q == 0) {
#pragma unroll
        for (int k = 0; k < 3; k++) {
            sKEY[r1 * 6 + chalf * 3 + k] = k1[k];
            sKEY[r2 * 6 + chalf * 3 + k] = k2[k];
        }
    }
    __syncthreads();   // also orders the lo-image stores before the tail reads

    // -------- per-row candidates + exact fp32 re-check (4 threads/row) -------
    {
        int row = tid >> 2;       // 512 threads -> 128 rows
        int sub = tid & 3;
        u32 kk[6];
#pragma unroll
        for (int j = 0; j < 6; j++) kk[j] = sKEY[row * 6 + j];
        u32 kmin = kk[0];
#pragma unroll
        for (int j = 1; j < 6; j++) kmin = umin(kmin, kk[j]);
        float thr = __uint_as_float(kmin & 0xFFFFFE00u) + MARGIN;

        int cidx[6]; int cnt = 0;
#pragma unroll
        for (int j = 0; j < 6; j++) {
            if (__uint_as_float(kk[j] & 0xFFFFFE00u) <= thr) {
                int c = (int)(kk[j] & 511u);
                bool dup = false;
                for (int p = 0; p < cnt; p++) dup |= (cidx[p] == c);
                if (!dup) cidx[cnt++] = c;
            }
        }

        int bestI;
        if (cnt == 1) {
            bestI = cidx[0];
        } else {
            // vx is constant across candidates -> rank by (ee - 2*dot) only
            float dots[6];
#pragma unroll
            for (int j = 0; j < 6; j++) dots[j] = 0.0f;
            for (int i = 0; i < 16; i++) {
                int w = sub * 16 + i;
                u32 hw = *(const u32*)(sc + REG_A + (u32)row * 272 + (u32)w * 4);
                u32 lw = *(const u32*)(sc + REG_A + 34816 + (u32)row * 272 + (u32)w * 4);
                __half2 hh = *reinterpret_cast<__half2*>(&hw);
                __half2 ll = *reinterpret_cast<__half2*>(&lw);
                float x0 = __half2float(hh.x) + __half2float(ll.x);
                float x1 = __half2float(hh.y) + __half2float(ll.y);
                for (int j = 0; j < cnt; j++) {
                    const float* ep = emb + (size_t)cidx[j] * H_DIM + 2 * w;
                    dots[j] = fmaf(x0, __ldg(ep),     dots[j]);
                    dots[j] = fmaf(x1, __ldg(ep + 1), dots[j]);
                }
            }
            for (int j = 0; j < cnt; j++) {
                dots[j] += __shfl_xor_sync(0xFFFFFFFFu, dots[j], 1);
                dots[j] += __shfl_xor_sync(0xFFFFFFFFu, dots[j], 2);
            }
            float bestD = __int_as_float(0x7f800000);
            bestI = 0x7fffffff;
            for (int j = 0; j < cnt; j++) {
                float dd = __fsub_rn(sEE[cidx[j]], __fmul_rn(2.0f, dots[j]));
                if (dd < bestD || (dd == bestD && cidx[j] < bestI)) { bestD = dd; bestI = cidx[j]; }
            }
        }

        if (sub == 0) {
            int gr = rowBase + row;
            float4 p0 = *(const float4*)(g_probs + bestI * A_DIM);
            float4 p1 = *(const float4*)(g_probs + bestI * A_DIM + 4);
            float4* po = (float4*)out;
            po[gr * 2 + 0] = p0;
            po[gr * 2 + 1] = p1;
            out[(size_t)N_ROWS * A_DIM + gr] = g_value[bestI];
        }
    }
}

// ===================== launch =====================
extern "C" void kernel_launch(void* const* d_in, const int* in_sizes, int n_in,
                              void* d_out, int out_size)
{
    const float* inputs = (const float*)d_in[0];
    const float* W1  = (const float*)d_in[1];
    const float* b1  = (const float*)d_in[2];
    const float* Wh  = (const float*)d_in[3];
    const float* bh  = (const float*)d_in[4];
    const float* emb = (const float*)d_in[5];
    const float* Wa  = (const float*)d_in[6];
    const float* ba  = (const float*)d_in[7];
    const float* Wv  = (const float*)d_in[8];
    const float* bv  = (const float*)d_in[9];

    cudaFuncSetAttribute(fused_kernel,
                         cudaFuncAttributeMaxDynamicSharedMemorySize, SMEM_BYTES);

    prep_all<<<416, 256>>>(emb, Wa, ba, Wv, bv, W1, Wh);
    fused_kernel<<<N_ROWS / TM, NTHREADS, SMEM_BYTES>>>(
        inputs, b1, bh, emb, (float*)d_out);
}

// round 16
// speedup vs baseline: 1.0331x; 1.0331x over previous
#include <cuda_runtime.h>
#include <cuda_fp16.h>
#include <math.h>
#include <stdint.h>

#define N_ROWS  131072
#define S_DIM   64
#define H_DIM   128
#define K_CODES 512
#define A_DIM   8
#define TM      128
#define NTHREADS 512
#define MARGIN  0.05f

typedef uint32_t u32;

// ===================== warp-level tensor ops (base PTX) =====================
#define LDSM4(r, addr)                                                        \
    asm volatile("ldmatrix.sync.aligned.m8n8.x4.shared.b16 {%0,%1,%2,%3}, [%4];" \
                 : "=r"((r)[0]), "=r"((r)[1]), "=r"((r)[2]), "=r"((r)[3])     \
                 : "r"(addr))

__device__ __forceinline__ void mma16816(float* c, const u32* a, u32 b0, u32 b1) {
    asm volatile("mma.sync.aligned.m16n8k16.row.col.f32.f16.f16.f32 "
                 "{%0,%1,%2,%3}, {%4,%5,%6,%7}, {%8,%9}, {%0,%1,%2,%3};"
                 : "+f"(c[0]), "+f"(c[1]), "+f"(c[2]), "+f"(c[3])
                 : "r"(a[0]), "r"(a[1]), "r"(a[2]), "r"(a[3]), "r"(b0), "r"(b1));
}

__device__ __forceinline__ u32 smem_u32(const void* p) {
    u32 a; asm("{ .reg .u64 t; cvta.to.shared.u64 t, %1; cvt.u32.u64 %0, t; }"
               : "=r"(a) : "l"(p)); return a;
}
__device__ __forceinline__ u32 pkh(float a, float b) {
    __half2 t; t.x = __float2half_rn(a); t.y = __float2half_rn(b);
    return *reinterpret_cast<u32*>(&t);
}
__device__ __forceinline__ void cpa16(u32 dst, const void* src) {
    asm volatile("cp.async.cg.shared.global [%0], [%1], 16;"
                 :: "r"(dst), "l"(src) : "memory");
}
#define CP_COMMIT() asm volatile("cp.async.commit_group;" ::: "memory")
#define CP_WAIT(n)  asm volatile("cp.async.wait_group %0;" :: "n"(n) : "memory")

// branchless top-3 insert of packed key (float-bits masked | code), ascending
__device__ __forceinline__ void key3(u32 k, u32* t) {
    u32 a = umin(t[0], k);
    u32 b = umax(t[0], k);
    t[0] = a;
    u32 c = umin(t[1], b);
    u32 d = umax(t[1], b);
    t[1] = c;
    t[2] = umin(t[2], d);
}

// ===================== device globals =====================
__device__ float g_ee[K_CODES];
__device__ float g_probs[K_CODES * A_DIM];
__device__ float g_value[K_CODES];

// fp16 images:  W1T hi/lo (pitch 72), WhT hi/lo (pitch 136), E hi-only (4 x [128][136])
#define IMG_W1 0
#define IMG_WH 18432
#define IMG_E  53248
__device__ __half g_img[122880];

// ===================== kernel 1: merged prelim =====================
__global__ void prep_all(const float* __restrict__ emb,
                         const float* __restrict__ Wa, const float* __restrict__ ba,
                         const float* __restrict__ Wv, const float* __restrict__ bv,
                         const float* __restrict__ W1, const float* __restrict__ Wh)
{
    if (blockIdx.x < 64) {
        int code = blockIdx.x * 8 + (threadIdx.x >> 5);
        int lane = threadIdx.x & 31;
        const float* e = emb + code * H_DIM;
        double ee = 0.0;
        float logit[A_DIM];
#pragma unroll
        for (int a = 0; a < A_DIM; a++) logit[a] = 0.0f;
        float val = 0.0f;
#pragma unroll
        for (int j = 0; j < 4; j++) {
            int d = lane + 32 * j;
            float ej = e[d];
            ee += (double)ej * (double)ej;
#pragma unroll
            for (int a = 0; a < A_DIM; a++) logit[a] = fmaf(ej, Wa[d * A_DIM + a], logit[a]);
            val = fmaf(ej, Wv[d], val);
        }
#pragma unroll
        for (int off = 16; off; off >>= 1) {
            ee  += __shfl_xor_sync(0xFFFFFFFFu, ee,  off);
            val += __shfl_xor_sync(0xFFFFFFFFu, val, off);
#pragma unroll
            for (int a = 0; a < A_DIM; a++)
                logit[a] += __shfl_xor_sync(0xFFFFFFFFu, logit[a], off);
        }
        if (lane == 0) {
#pragma unroll
            for (int a = 0; a < A_DIM; a++) logit[a] += ba[a];
            g_ee[code] = (float)ee;
            g_value[code] = val + bv[0];
            float m = logit[0];
#pragma unroll
            for (int a = 1; a < A_DIM; a++) m = fmaxf(m, logit[a]);
            float p[A_DIM], s = 0.0f;
#pragma unroll
            for (int a = 0; a < A_DIM; a++) { p[a] = expf(logit[a] - m); s += p[a]; }
#pragma unroll
            for (int a = 0; a < A_DIM; a++) g_probs[code * A_DIM + a] = p[a] / s;
        }
        return;
    }
    int idx = (blockIdx.x - 64) * 256 + threadIdx.x;
    if (idx < 8192) {                       // W1T hi/lo
        int n = idx >> 6, s = idx & 63;
        float v = W1[s * H_DIM + n];
        __half h = __float2half_rn(v);
        __half l = __float2half_rn(v - __half2float(h));
        int o = n * 72 + s;
        g_img[IMG_W1 + o] = h;
        g_img[IMG_W1 + 9216 + o] = l;
    } else if (idx < 24576) {               // WhT hi/lo
        int j = idx - 8192;
        int n = j >> 7, k = j & 127;
        float v = Wh[k * H_DIM + n];
        __half h = __float2half_rn(v);
        __half l = __float2half_rn(v - __half2float(h));
        int o = n * 136 + k;
        g_img[IMG_WH + o] = h;
        g_img[IMG_WH + 17408 + o] = l;
    } else if (idx < 90112) {               // E hi only
        int j = idx - 24576;
        int g = j >> 7, d = j & 127;
        int t = g >> 7, c = g & 127;
        g_img[IMG_E + t * 17408 + c * 136 + d] = __float2half_rn(emb[g * H_DIM + d]);
    }
}

// ===================== kernel 2: fused main =====================
#define OFF_B1   0        // float[128]
#define OFF_BH   512
#define OFF_VV   1024     // float[128][2]
#define OFF_EE   2048     // float[512]
#define OFF_KEY  4096     // u32[128][6] = 3072 B
#define REG_A    7168     // input hi|lo(+18432) p144; W1 hi(+36864)|lo(+55296); later x2 hi|lo(+34816) p272
#define REG_C    80896    // x1 hi|lo(+34816) p272; later E hi tiles 0(+0),1(+34816)
#define REG_D    150528   // Wh hi|lo(+34816) p272; later E hi tiles 2(+0),3(+34816)
#define SMEM_BYTES 220160

// 3-pass split GEMM, warp tile 16x64 (encoder)
template<int KS>
__device__ __forceinline__ void run_gemm4(u32 aH, u32 aL, u32 bH, u32 bL,
                                          int pitchA, int pitchB,
                                          int lane, int wrow, int cbase, float (*acc)[4])
{
    const u32 aoff = (u32)(wrow + (lane & 15)) * pitchA + (u32)(lane >> 4) * 16;
    const u32 boff = (u32)(cbase + (lane & 7) + ((lane >> 4) << 3)) * pitchB
                   + (u32)((lane >> 3) & 1) * 16;
#pragma unroll
    for (int ks = 0; ks < KS; ks++) {
        u32 ah[4], al[4];
        LDSM4(ah, aH + aoff + ks * 32);
        LDSM4(al, aL + aoff + ks * 32);
#pragma unroll
        for (int half = 0; half < 2; half++) {
            const u32 base = boff + (u32)(half * 2) * 16 * pitchB + ks * 32;
            u32 bh0[4], bh1[4], bl0[4], bl1[4];
            LDSM4(bh0, bH + base);
            LDSM4(bh1, bH + base + 16u * pitchB);
            float* a0 = acc[half * 4 + 0];
            float* a1 = acc[half * 4 + 1];
            float* a2 = acc[half * 4 + 2];
            float* a3 = acc[half * 4 + 3];
            mma16816(a0, ah, bh0[0], bh0[1]);
            mma16816(a1, ah, bh0[2], bh0[3]);
            mma16816(a2, ah, bh1[0], bh1[1]);
            mma16816(a3, ah, bh1[2], bh1[3]);
            mma16816(a0, al, bh0[0], bh0[1]);
            mma16816(a1, al, bh0[2], bh0[3]);
            mma16816(a2, al, bh1[0], bh1[1]);
            mma16816(a3, al, bh1[2], bh1[3]);
            LDSM4(bl0, bL + base);
            LDSM4(bl1, bL + base + 16u * pitchB);
            mma16816(a0, ah, bl0[0], bl0[1]);
            mma16816(a1, ah, bl0[2], bl0[3]);
            mma16816(a2, ah, bl1[0], bl1[1]);
            mma16816(a3, ah, bl1[2], bl1[3]);
        }
    }
}

// hi-only score GEMM, warp tile 16x64, A from smem
__device__ __forceinline__ void run_gemm_hi(u32 aH, u32 bH,
                                            int pitchA, int pitchB,
                                            int lane, int wrow, int cbase, float (*acc)[4])
{
    const u32 aoff = (u32)(wrow + (lane & 15)) * pitchA + (u32)(lane >> 4) * 16;
    const u32 boff = (u32)(cbase + (lane & 7) + ((lane >> 4) << 3)) * pitchB
                   + (u32)((lane >> 3) & 1) * 16;
#pragma unroll
    for (int ks = 0; ks < 8; ks++) {
        u32 ah[4];
        LDSM4(ah, aH + aoff + ks * 32);
#pragma unroll
        for (int bt = 0; bt < 4; bt++) {
            u32 bh[4];
            LDSM4(bh, bH + boff + (u32)bt * 16 * pitchB + ks * 32);
            mma16816(acc[2 * bt],     ah, bh[0], bh[1]);
            mma16816(acc[2 * bt + 1], ah, bh[2], bh[3]);
        }
    }
}

__global__ __launch_bounds__(NTHREADS, 1)
void fused_kernel(const float* __restrict__ in,
                  const float* __restrict__ b1, const float* __restrict__ bh,
                  const float* __restrict__ emb,
                  float* __restrict__ out)
{
    extern __shared__ __align__(16) unsigned char smem[];
    const u32 sb = smem_u32(smem);
    char* sc = (char*)smem;

    const int tid   = threadIdx.x;
    const int wid   = tid >> 5;
    const int lane  = tid & 31;
    const int g     = lane >> 2;
    const int q     = lane & 3;
    const int wrow  = (wid & 7) * 16;      // row strip
    const int chalf = wid >> 3;            // column half
    const int cbase = chalf * 64;
    const int r1 = wrow + g, r2 = r1 + 8;
    const int rowBase = blockIdx.x * TM;

    float* sB1  = (float*)(sc + OFF_B1);
    float* sBH  = (float*)(sc + OFF_BH);
    float* sVV  = (float*)(sc + OFF_VV);
    float* sEE  = (float*)(sc + OFF_EE);
    u32*   sKEY = (u32*)  (sc + OFF_KEY);

    const char* gimg = (const char*)g_img;

    // ---------------- Stage 0: prefetch W1, Wh; split input ----------------
    for (int i = tid; i < 2304; i += NTHREADS)
        cpa16(sb + REG_A + 36864 + i * 16, gimg + IMG_W1 * 2 + i * 16);
    CP_COMMIT();
    for (int i = tid; i < 4352; i += NTHREADS)
        cpa16(sb + REG_D + i * 16, gimg + IMG_WH * 2 + i * 16);
    CP_COMMIT();

    for (int p = tid; p < 128 * 32; p += NTHREADS) {
        int row = p >> 5, pc = p & 31;
        float2 v = *(const float2*)(in + (size_t)(rowBase + row) * S_DIM + 2 * pc);
        __half h0 = __float2half_rn(v.x);
        __half h1 = __float2half_rn(v.y);
        u32 o = (u32)row * 144 + (u32)pc * 4;
        *(u32*)(sc + REG_A + o)         = pkh(__half2float(h0), __half2float(h1));
        *(u32*)(sc + REG_A + 18432 + o) = pkh(v.x - __half2float(h0), v.y - __half2float(h1));
    }
    if (tid < 128) { sB1[tid] = b1[tid]; sBH[tid] = bh[tid]; }
    if (tid < 512) sEE[tid] = g_ee[tid];
    CP_WAIT(1);
    __syncthreads();

    float accA[8][4];

    // ---------------- Stage 1: x1 = relu(in @ W1 + b1) ----------------
#pragma unroll
    for (int t = 0; t < 8; t++)
#pragma unroll
        for (int j = 0; j < 4; j++) accA[t][j] = 0.0f;
    run_gemm4<4>(sb + REG_A, sb + REG_A + 18432,
                 sb + REG_A + 36864, sb + REG_A + 55296, 144, 144, lane, wrow, cbase, accA);
#pragma unroll
    for (int t = 0; t < 8; t++) {
        int c = cbase + 8 * t + 2 * q;
        float z0 = fmaxf(accA[t][0] + sB1[c],     0.0f);
        float z1 = fmaxf(accA[t][1] + sB1[c + 1], 0.0f);
        float z2 = fmaxf(accA[t][2] + sB1[c],     0.0f);
        float z3 = fmaxf(accA[t][3] + sB1[c + 1], 0.0f);
        __half h0 = __float2half_rn(z0), h1 = __float2half_rn(z1);
        __half h2 = __float2half_rn(z2), h3 = __float2half_rn(z3);
        u32 o1 = (u32)r1 * 272 + (u32)c * 2;
        u32 o2 = (u32)r2 * 272 + (u32)c * 2;
        *(u32*)(sc + REG_C + o1)         = pkh(__half2float(h0), __half2float(h1));
        *(u32*)(sc + REG_C + o2)         = pkh(__half2float(h2), __half2float(h3));
        *(u32*)(sc + REG_C + 34816 + o1) = pkh(z0 - __half2float(h0), z1 - __half2float(h1));
        *(u32*)(sc + REG_C + 34816 + o2) = pkh(z2 - __half2float(h2), z3 - __half2float(h3));
    }
    CP_WAIT(0);
    __syncthreads();

    // ---------------- Stage 2: x2 = relu(x1 @ Wh + bh) ----------------
#pragma unroll
    for (int t = 0; t < 8; t++)
#pragma unroll
        for (int j = 0; j < 4; j++) accA[t][j] = 0.0f;
    run_gemm4<8>(sb + REG_C, sb + REG_C + 34816,
                 sb + REG_D, sb + REG_D + 34816, 272, 272, lane, wrow, cbase, accA);
    __syncthreads();   // MMA reads of REG_C/REG_D complete

    // prefetch all 4 E hi tiles: 0,1 -> REG_C; 2,3 -> REG_D
#pragma unroll
    for (int t4 = 0; t4 < 4; t4++) {
        u32 dst = ((t4 < 2) ? (sb + REG_C) : (sb + REG_D)) + (u32)(t4 & 1) * 34816;
        const char* src = gimg + (IMG_E + t4 * 17408) * 2;
        for (int i = tid; i < 2176; i += NTHREADS)
            cpa16(dst + i * 16, src + i * 16);
    }
    CP_COMMIT();

    // stage 2 epilogue (overlaps fills): relu+bias, split x2 -> REG_A, vv partials
    {
        float vp1 = 0.0f, vp2 = 0.0f;
#pragma unroll
        for (int t = 0; t < 8; t++) {
            int c = cbase + 8 * t + 2 * q;
            float z0 = fmaxf(accA[t][0] + sBH[c],     0.0f);
            float z1 = fmaxf(accA[t][1] + sBH[c + 1], 0.0f);
            float z2 = fmaxf(accA[t][2] + sBH[c],     0.0f);
            float z3 = fmaxf(accA[t][3] + sBH[c + 1], 0.0f);
            __half h0 = __float2half_rn(z0), h1 = __float2half_rn(z1);
            __half h2 = __float2half_rn(z2), h3 = __float2half_rn(z3);
            float fl0 = z0 - __half2float(h0), fl1 = z1 - __half2float(h1);
            float fl2 = z2 - __half2float(h2), fl3 = z3 - __half2float(h3);
            float x0 = __half2float(h0) + __half2float(__float2half_rn(fl0));
            float x1 = __half2float(h1) + __half2float(__float2half_rn(fl1));
            float x2 = __half2float(h2) + __half2float(__float2half_rn(fl2));
            float x3 = __half2float(h3) + __half2float(__float2half_rn(fl3));
            vp1 = fmaf(x0, x0, vp1); vp1 = fmaf(x1, x1, vp1);
            vp2 = fmaf(x2, x2, vp2); vp2 = fmaf(x3, x3, vp2);
            u32 o1 = (u32)r1 * 272 + (u32)c * 2;
            u32 o2 = (u32)r2 * 272 + (u32)c * 2;
            *(u32*)(sc + REG_A + o1)         = pkh(__half2float(h0), __half2float(h1));
            *(u32*)(sc + REG_A + o2)         = pkh(__half2float(h2), __half2float(h3));
            *(u32*)(sc + REG_A + 34816 + o1) = pkh(fl0, fl1);
            *(u32*)(sc + REG_A + 34816 + o2) = pkh(fl2, fl3);
        }
        vp1 += __shfl_xor_sync(0xFFFFFFFFu, vp1, 1);
        vp1 += __shfl_xor_sync(0xFFFFFFFFu, vp1, 2);
        vp2 += __shfl_xor_sync(0xFFFFFFFFu, vp2, 1);
        vp2 += __shfl_xor_sync(0xFFFFFFFFu, vp2, 2);
        if (q == 0) { sVV[r1 * 2 + chalf] = vp1; sVV[r2 * 2 + chalf] = vp2; }
    }
    CP_WAIT(0);
    __syncthreads();   // x2 image + vv + ALL E tiles ready; nothing rewritten below

    // ---------------- Score: 4 tiles, acc ping-pong (GEMM t+1 || select t) ----
    const float vva = sVV[r1 * 2] + sVV[r1 * 2 + 1];
    const float vvb = sVV[r2 * 2] + sVV[r2 * 2 + 1];
    u32 k1[3] = {0xFFFFFFFFu, 0xFFFFFFFFu, 0xFFFFFFFFu};
    u32 k2[3] = {0xFFFFFFFFu, 0xFFFFFFFFu, 0xFFFFFFFFu};
    float accB[8][4];

#define TILE_BUF(T) ((((T) < 2) ? (sb + REG_C) : (sb + REG_D)) + (u32)((T) & 1) * 34816)

#define ZERO_ACC(A)                                                           \
    do {                                                                      \
        _Pragma("unroll")                                                     \
        for (int t = 0; t < 8; t++)                                           \
            _Pragma("unroll")                                                 \
            for (int j = 0; j < 4; j++) (A)[t][j] = 0.0f;                     \
    } while (0)

#define SELECT(A, T)                                                          \
    do {                                                                      \
        int codeBase = (T) * 128 + cbase;                                     \
        _Pragma("unroll")                                                     \
        for (int t = 0; t < 8; t++) {                                         \
            int c = codeBase + 8 * t + 2 * q;                                 \
            _Pragma("unroll")                                                 \
            for (int jj = 0; jj < 2; jj++) {                                  \
                int code = c + jj;                                            \
                float ee = sEE[code];                                         \
                float da = fmaf(-2.0f, (A)[t][jj],     vva) + ee;             \
                float db = fmaf(-2.0f, (A)[t][2 + jj], vvb) + ee;             \
                key3((__float_as_uint(da) & 0xFFFFFE00u) | (u32)code, k1);    \
                key3((__float_as_uint(db) & 0xFFFFFE00u) | (u32)code, k2);    \
            }                                                                 \
        }                                                                     \
    } while (0)

    ZERO_ACC(accA);
    run_gemm_hi(sb + REG_A, TILE_BUF(0), 272, 272, lane, wrow, cbase, accA);
    ZERO_ACC(accB);
    run_gemm_hi(sb + REG_A, TILE_BUF(1), 272, 272, lane, wrow, cbase, accB);
    SELECT(accA, 0);
    ZERO_ACC(accA);
    run_gemm_hi(sb + REG_A, TILE_BUF(2), 272, 272, lane, wrow, cbase, accA);
    SELECT(accB, 1);
    ZERO_ACC(accB);
    run_gemm_hi(sb + REG_A, TILE_BUF(3), 272, 272, lane, wrow, cbase, accB);
    SELECT(accA, 2);
    SELECT(accB, 3);

    // merge top-3 across the 4 q lanes of each row half
#pragma unroll
    for (int mk = 1; mk <= 2; mk <<= 1) {
#pragma unroll
        for (int k = 0; k < 3; k++) {
            u32 o1 = __shfl_xor_sync(0xFFFFFFFFu, k1[k], mk);
            u32 o2 = __shfl_xor_sync(0xFFFFFFFFu, k2[k], mk);
            key3(o1, k1);
            key3(o2, k2);
        }
    }
    if (q == 0) {
#pragma unroll
        for (int k = 0; k < 3; k++) {
            sKEY[r1 * 6 + chalf * 3 + k] = k1[k];
            sKEY[r2 * 6 + chalf * 3 + k] = k2[k];
        }
    }
    __syncthreads();

    // -------- per-row candidates + exact fp32 re-check (4 threads/row) -------
    {
        int row = tid >> 2;       // 512 threads -> 128 rows
        int sub = tid & 3;
        u32 kk[6];
#pragma unroll
        for (int j = 0; j < 6; j++) kk[j] = sKEY[row * 6 + j];
        u32 kmin = kk[0];
#pragma unroll
        for (int j = 1; j < 6; j++) kmin = umin(kmin, kk[j]);
        float thr = __uint_as_float(kmin & 0xFFFFFE00u) + MARGIN;

        int cidx[6]; int cnt = 0;
#pragma unroll
        for (int j = 0; j < 6; j++) {
            if (__uint_as_float(kk[j] & 0xFFFFFE00u) <= thr) {
                int c = (int)(kk[j] & 511u);
                bool dup = false;
                for (int p = 0; p < cnt; p++) dup |= (cidx[p] == c);
                if (!dup) cidx[cnt++] = c;
            }
        }

        int bestI;
        if (cnt == 1) {
            bestI = cidx[0];
        } else {
            // vx is constant across candidates -> rank by (ee - 2*dot) only
            // (validated flip-free in R15: rel_err bit-identical)
            float dots[6];
#pragma unroll
            for (int j = 0; j < 6; j++) dots[j] = 0.0f;
            for (int i = 0; i < 16; i++) {
                int w = sub * 16 + i;
                u32 hw = *(const u32*)(sc + REG_A + (u32)row * 272 + (u32)w * 4);
                u32 lw = *(const u32*)(sc + REG_A + 34816 + (u32)row * 272 + (u32)w * 4);
                __half2 hh = *reinterpret_cast<__half2*>(&hw);
                __half2 ll = *reinterpret_cast<__half2*>(&lw);
                float x0 = __half2float(hh.x) + __half2float(ll.x);
                float x1 = __half2float(hh.y) + __half2float(ll.y);
                for (int j = 0; j < cnt; j++) {
                    const float* ep = emb + (size_t)cidx[j] * H_DIM + 2 * w;
                    dots[j] = fmaf(x0, __ldg(ep),     dots[j]);
                    dots[j] = fmaf(x1, __ldg(ep + 1), dots[j]);
                }
            }
            for (int j = 0; j < cnt; j++) {
                dots[j] += __shfl_xor_sync(0xFFFFFFFFu, dots[j], 1);
                dots[j] += __shfl_xor_sync(0xFFFFFFFFu, dots[j], 2);
            }
            float bestD = __int_as_float(0x7f800000);
            bestI = 0x7fffffff;
            for (int j = 0; j < cnt; j++) {
                float dd = __fsub_rn(sEE[cidx[j]], __fmul_rn(2.0f, dots[j]));
                if (dd < bestD || (dd == bestD && cidx[j] < bestI)) { bestD = dd; bestI = cidx[j]; }
            }
        }

        if (sub == 0) {
            int gr = rowBase + row;
            float4 p0 = *(const float4*)(g_probs + bestI * A_DIM);
            float4 p1 = *(const float4*)(g_probs + bestI * A_DIM + 4);
            float4* po = (float4*)out;
            po[gr * 2 + 0] = p0;
            po[gr * 2 + 1] = p1;
            out[(size_t)N_ROWS * A_DIM + gr] = g_value[bestI];
        }
    }
}

// ===================== launch =====================
extern "C" void kernel_launch(void* const* d_in, const int* in_sizes, int n_in,
                              void* d_out, int out_size)
{
    const float* inputs = (const float*)d_in[0];
    const float* W1  = (const float*)d_in[1];
    const float* b1  = (const float*)d_in[2];
    const float* Wh  = (const float*)d_in[3];
    const float* bh  = (const float*)d_in[4];
    const float* emb = (const float*)d_in[5];
    const float* Wa  = (const float*)d_in[6];
    const float* ba  = (const float*)d_in[7];
    const float* Wv  = (const float*)d_in[8];
    const float* bv  = (const float*)d_in[9];

    cudaFuncSetAttribute(fused_kernel,
                         cudaFuncAttributeMaxDynamicSharedMemorySize, SMEM_BYTES);

    prep_all<<<416, 256>>>(emb, Wa, ba, Wv, bv, W1, Wh);
    fused_kernel<<<N_ROWS / TM, NTHREADS, SMEM_BYTES>>>(
        inputs, b1, bh, emb, (float*)d_out);
}

// round 17
// speedup vs baseline: 1.0363x; 1.0031x over previous
#include <cuda_runtime.h>
#include <cuda_fp16.h>
#include <math.h>
#include <stdint.h>

#define N_ROWS  131072
#define S_DIM   64
#define H_DIM   128
#define K_CODES 512
#define A_DIM   8
#define TM      64
#define NTHREADS 256
#define MARGIN  0.05f

typedef uint32_t u32;

// ===================== warp-level tensor ops (base PTX) =====================
#define LDSM4(r, addr)                                                        \
    asm volatile("ldmatrix.sync.aligned.m8n8.x4.shared.b16 {%0,%1,%2,%3}, [%4];" \
                 : "=r"((r)[0]), "=r"((r)[1]), "=r"((r)[2]), "=r"((r)[3])     \
                 : "r"(addr))

__device__ __forceinline__ void mma16816(float* c, const u32* a, u32 b0, u32 b1) {
    asm volatile("mma.sync.aligned.m16n8k16.row.col.f32.f16.f16.f32 "
                 "{%0,%1,%2,%3}, {%4,%5,%6,%7}, {%8,%9}, {%0,%1,%2,%3};"
                 : "+f"(c[0]), "+f"(c[1]), "+f"(c[2]), "+f"(c[3])
                 : "r"(a[0]), "r"(a[1]), "r"(a[2]), "r"(a[3]), "r"(b0), "r"(b1));
}

__device__ __forceinline__ u32 smem_u32(const void* p) {
    u32 a; asm("{ .reg .u64 t; cvta.to.shared.u64 t, %1; cvt.u32.u64 %0, t; }"
               : "=r"(a) : "l"(p)); return a;
}
__device__ __forceinline__ u32 pkh(float a, float b) {
    __half2 t; t.x = __float2half_rn(a); t.y = __float2half_rn(b);
    return *reinterpret_cast<u32*>(&t);
}
__device__ __forceinline__ void cpa16(u32 dst, const void* src) {
    asm volatile("cp.async.cg.shared.global [%0], [%1], 16;"
                 :: "r"(dst), "l"(src) : "memory");
}
#define CP_COMMIT() asm volatile("cp.async.commit_group;" ::: "memory")
#define CP_WAIT(n)  asm volatile("cp.async.wait_group %0;" :: "n"(n) : "memory")

// branchless top-3 insert of packed key (float-bits masked | code), ascending
__device__ __forceinline__ void key3(u32 k, u32* t) {
    u32 a = umin(t[0], k);
    u32 b = umax(t[0], k);
    t[0] = a;
    u32 c = umin(t[1], b);
    u32 d = umax(t[1], b);
    t[1] = c;
    t[2] = umin(t[2], d);
}

// ===================== device globals =====================
__device__ float g_ee[K_CODES];
__device__ float g_probs[K_CODES * A_DIM];
__device__ float g_value[K_CODES];

// fp16 images (halves):
//  W1T  hi [0,9216), lo [9216,18432)                (pitch 72, [128n][64k])
//  WhT  2 K-chunks: c at 18432+c*18432, hi then lo  (pitch 72, [128n][64k])
//  E    4 tiles hi-only at 55296+t*17408            (pitch 136, [128c][128d])
#define IMG_W1 0
#define IMG_WH 18432
#define IMG_E  55296
__device__ __half g_img[124928];

// ===================== kernel 1: merged prelim =====================
__global__ void prep_all(const float* __restrict__ emb,
                         const float* __restrict__ Wa, const float* __restrict__ ba,
                         const float* __restrict__ Wv, const float* __restrict__ bv,
                         const float* __restrict__ W1, const float* __restrict__ Wh)
{
    if (blockIdx.x < 64) {
        int code = blockIdx.x * 8 + (threadIdx.x >> 5);
        int lane = threadIdx.x & 31;
        const float* e = emb + code * H_DIM;
        double ee = 0.0;
        float logit[A_DIM];
#pragma unroll
        for (int a = 0; a < A_DIM; a++) logit[a] = 0.0f;
        float val = 0.0f;
#pragma unroll
        for (int j = 0; j < 4; j++) {
            int d = lane + 32 * j;
            float ej = e[d];
            ee += (double)ej * (double)ej;
#pragma unroll
            for (int a = 0; a < A_DIM; a++) logit[a] = fmaf(ej, Wa[d * A_DIM + a], logit[a]);
            val = fmaf(ej, Wv[d], val);
        }
#pragma unroll
        for (int off = 16; off; off >>= 1) {
            ee  += __shfl_xor_sync(0xFFFFFFFFu, ee,  off);
            val += __shfl_xor_sync(0xFFFFFFFFu, val, off);
#pragma unroll
            for (int a = 0; a < A_DIM; a++)
                logit[a] += __shfl_xor_sync(0xFFFFFFFFu, logit[a], off);
        }
        if (lane == 0) {
#pragma unroll
            for (int a = 0; a < A_DIM; a++) logit[a] += ba[a];
            g_ee[code] = (float)ee;
            g_value[code] = val + bv[0];
            float m = logit[0];
#pragma unroll
            for (int a = 1; a < A_DIM; a++) m = fmaxf(m, logit[a]);
            float p[A_DIM], s = 0.0f;
#pragma unroll
            for (int a = 0; a < A_DIM; a++) { p[a] = expf(logit[a] - m); s += p[a]; }
#pragma unroll
            for (int a = 0; a < A_DIM; a++) g_probs[code * A_DIM + a] = p[a] / s;
        }
        return;
    }
    int idx = (blockIdx.x - 64) * 256 + threadIdx.x;
    if (idx < 8192) {                       // W1T hi/lo
        int n = idx >> 6, s = idx & 63;
        float v = W1[s * H_DIM + n];
        __half h = __float2half_rn(v);
        __half l = __float2half_rn(v - __half2float(h));
        int o = n * 72 + s;
        g_img[IMG_W1 + o] = h;
        g_img[IMG_W1 + 9216 + o] = l;
    } else if (idx < 24576) {               // WhT hi/lo, two K=64 chunks
        int j = idx - 8192;
        int n = j >> 7, k = j & 127;
        int c = k >> 6, kl = k & 63;
        float v = Wh[k * H_DIM + n];
        __half h = __float2half_rn(v);
        __half l = __float2half_rn(v - __half2float(h));
        int base = IMG_WH + c * 18432;
        int o = n * 72 + kl;
        g_img[base + o] = h;
        g_img[base + 9216 + o] = l;
    } else if (idx < 90112) {               // E hi only
        int j = idx - 24576;
        int g = j >> 7, d = j & 127;
        int t = g >> 7, c = g & 127;
        g_img[IMG_E + t * 17408 + c * 136 + d] = __float2half_rn(emb[g * H_DIM + d]);
    }
}

// ===================== kernel 2: fused main (TM=64, 2 CTAs/SM) ==============
#define OFF_B1   0        // float[128]
#define OFF_BH   512
#define OFF_VV   1024     // float[64][2]
#define OFF_EE   2048     // float[512]
#define OFF_KEY  4096     // u32[64][6] = 1536 B
#define REG_X    6144     // 34816: input hi|lo(+9216) p144; later x2 hi|lo(+17408) p272
#define REG_Y    40960    // 34816: x1 hi|lo(+17408) p272; later E tiles 0,2
#define REG_Z    75776    // 36864: W1 hi|lo(+18432); Wh chunks; later E tiles 1,3
#define SMEM_BYTES 112640

// 3-pass split GEMM, warp tile 16x64
template<int KS>
__device__ __forceinline__ void run_gemm4(u32 aH, u32 aL, u32 bH, u32 bL,
                                          int pitchA, int pitchB,
                                          int lane, int wrow, int cbase, float (*acc)[4])
{
    const u32 aoff = (u32)(wrow + (lane & 15)) * pitchA + (u32)(lane >> 4) * 16;
    const u32 boff = (u32)(cbase + (lane & 7) + ((lane >> 4) << 3)) * pitchB
                   + (u32)((lane >> 3) & 1) * 16;
#pragma unroll
    for (int ks = 0; ks < KS; ks++) {
        u32 ah[4], al[4];
        LDSM4(ah, aH + aoff + ks * 32);
        LDSM4(al, aL + aoff + ks * 32);
#pragma unroll
        for (int half = 0; half < 2; half++) {
            const u32 base = boff + (u32)(half * 2) * 16 * pitchB + ks * 32;
            u32 bh0[4], bh1[4], bl0[4], bl1[4];
            LDSM4(bh0, bH + base);
            LDSM4(bh1, bH + base + 16u * pitchB);
            float* a0 = acc[half * 4 + 0];
            float* a1 = acc[half * 4 + 1];
            float* a2 = acc[half * 4 + 2];
            float* a3 = acc[half * 4 + 3];
            mma16816(a0, ah, bh0[0], bh0[1]);
            mma16816(a1, ah, bh0[2], bh0[3]);
            mma16816(a2, ah, bh1[0], bh1[1]);
            mma16816(a3, ah, bh1[2], bh1[3]);
            mma16816(a0, al, bh0[0], bh0[1]);
            mma16816(a1, al, bh0[2], bh0[3]);
            mma16816(a2, al, bh1[0], bh1[1]);
            mma16816(a3, al, bh1[2], bh1[3]);
            LDSM4(bl0, bL + base);
            LDSM4(bl1, bL + base + 16u * pitchB);
            mma16816(a0, ah, bl0[0], bl0[1]);
            mma16816(a1, ah, bl0[2], bl0[3]);
            mma16816(a2, ah, bl1[0], bl1[1]);
            mma16816(a3, ah, bl1[2], bl1[3]);
        }
    }
}

// hi-only score GEMM, warp tile 16x64
__device__ __forceinline__ void run_gemm_hi(u32 aH, u32 bH,
                                            int pitchA, int pitchB,
                                            int lane, int wrow, int cbase, float (*acc)[4])
{
    const u32 aoff = (u32)(wrow + (lane & 15)) * pitchA + (u32)(lane >> 4) * 16;
    const u32 boff = (u32)(cbase + (lane & 7) + ((lane >> 4) << 3)) * pitchB
                   + (u32)((lane >> 3) & 1) * 16;
#pragma unroll
    for (int ks = 0; ks < 8; ks++) {
        u32 ah[4];
        LDSM4(ah, aH + aoff + ks * 32);
#pragma unroll
        for (int bt = 0; bt < 4; bt++) {
            u32 bh[4];
            LDSM4(bh, bH + boff + (u32)bt * 16 * pitchB + ks * 32);
            mma16816(acc[2 * bt],     ah, bh[0], bh[1]);
            mma16816(acc[2 * bt + 1], ah, bh[2], bh[3]);
        }
    }
}

__global__ __launch_bounds__(NTHREADS, 2)
void fused_kernel(const float* __restrict__ in,
                  const float* __restrict__ b1, const float* __restrict__ bh,
                  const float* __restrict__ emb,
                  float* __restrict__ out)
{
    extern __shared__ __align__(16) unsigned char smem[];
    const u32 sb = smem_u32(smem);
    char* sc = (char*)smem;

    const int tid   = threadIdx.x;
    const int wid   = tid >> 5;
    const int lane  = tid & 31;
    const int g     = lane >> 2;
    const int q     = lane & 3;
    const int wrow  = (wid & 3) * 16;      // row strip (4 strips x 16 = 64 rows)
    const int chalf = wid >> 2;            // column half
    const int cbase = chalf * 64;
    const int r1 = wrow + g, r2 = r1 + 8;
    const int rowBase = blockIdx.x * TM;

    float* sB1  = (float*)(sc + OFF_B1);
    float* sBH  = (float*)(sc + OFF_BH);
    float* sVV  = (float*)(sc + OFF_VV);
    float* sEE  = (float*)(sc + OFF_EE);
    u32*   sKEY = (u32*)  (sc + OFF_KEY);

    const char* gimg = (const char*)g_img;

    // ---------------- Stage 0: prefetch W1; split input ----------------
    for (int i = tid; i < 2304; i += NTHREADS)          // W1 hi+lo (36864 B)
        cpa16(sb + REG_Z + i * 16, gimg + i * 16);
    CP_COMMIT();

    for (int p = tid; p < TM * 32; p += NTHREADS) {     // input split (64x64)
        int row = p >> 5, pc = p & 31;
        float2 v = *(const float2*)(in + (size_t)(rowBase + row) * S_DIM + 2 * pc);
        __half h0 = __float2half_rn(v.x);
        __half h1 = __float2half_rn(v.y);
        u32 o = (u32)row * 144 + (u32)pc * 4;
        *(u32*)(sc + REG_X + o)        = pkh(__half2float(h0), __half2float(h1));
        *(u32*)(sc + REG_X + 9216 + o) = pkh(v.x - __half2float(h0), v.y - __half2float(h1));
    }
    if (tid < 128) { sB1[tid] = b1[tid]; sBH[tid] = bh[tid]; }
    for (int i = tid; i < 512; i += NTHREADS) sEE[i] = g_ee[i];
    CP_WAIT(0);
    __syncthreads();

    float accA[8][4];

    // ---------------- Stage 1: x1 = relu(in @ W1 + b1) ----------------
#pragma unroll
    for (int t = 0; t < 8; t++)
#pragma unroll
        for (int j = 0; j < 4; j++) accA[t][j] = 0.0f;
    run_gemm4<4>(sb + REG_X, sb + REG_X + 9216,
                 sb + REG_Z, sb + REG_Z + 18432, 144, 144, lane, wrow, cbase, accA);
    __syncthreads();                                    // W1 (REG_Z) reads done
    for (int i = tid; i < 2304; i += NTHREADS)          // Wh chunk0 -> REG_Z
        cpa16(sb + REG_Z + i * 16, gimg + 36864 + i * 16);
    CP_COMMIT();

    // stage-1 epilogue (overlaps chunk0 fill): x1 -> REG_Y hi/lo p272
#pragma unroll
    for (int t = 0; t < 8; t++) {
        int c = cbase + 8 * t + 2 * q;
        float z0 = fmaxf(accA[t][0] + sB1[c],     0.0f);
        float z1 = fmaxf(accA[t][1] + sB1[c + 1], 0.0f);
        float z2 = fmaxf(accA[t][2] + sB1[c],     0.0f);
        float z3 = fmaxf(accA[t][3] + sB1[c + 1], 0.0f);
        __half h0 = __float2half_rn(z0), h1 = __float2half_rn(z1);
        __half h2 = __float2half_rn(z2), h3 = __float2half_rn(z3);
        u32 o1 = (u32)r1 * 272 + (u32)c * 2;
        u32 o2 = (u32)r2 * 272 + (u32)c * 2;
        *(u32*)(sc + REG_Y + o1)         = pkh(__half2float(h0), __half2float(h1));
        *(u32*)(sc + REG_Y + o2)         = pkh(__half2float(h2), __half2float(h3));
        *(u32*)(sc + REG_Y + 17408 + o1) = pkh(z0 - __half2float(h0), z1 - __half2float(h1));
        *(u32*)(sc + REG_Y + 17408 + o2) = pkh(z2 - __half2float(h2), z3 - __half2float(h3));
    }
    CP_WAIT(0);
    __syncthreads();

    // ---------------- Stage 2: x2 = relu(x1 @ Wh + bh), two K=64 chunks ------
#pragma unroll
    for (int t = 0; t < 8; t++)
#pragma unroll
        for (int j = 0; j < 4; j++) accA[t][j] = 0.0f;
    run_gemm4<4>(sb + REG_Y, sb + REG_Y + 17408,
                 sb + REG_Z, sb + REG_Z + 18432, 272, 144, lane, wrow, cbase, accA);
    __syncthreads();                                    // chunk0 reads done
    for (int i = tid; i < 2304; i += NTHREADS)          // Wh chunk1 -> REG_Z
        cpa16(sb + REG_Z + i * 16, gimg + 73728 + i * 16);
    CP_COMMIT();
    CP_WAIT(0);
    __syncthreads();
    run_gemm4<4>(sb + REG_Y + 128, sb + REG_Y + 17408 + 128,
                 sb + REG_Z, sb + REG_Z + 18432, 272, 144, lane, wrow, cbase, accA);
    __syncthreads();                                    // x1 (Y) + chunk1 (Z) reads done

    // prefetch E tiles 0 -> Y, 1 -> Z
    for (int i = tid; i < 2176; i += NTHREADS)
        cpa16(sb + REG_Y + i * 16, gimg + 110592 + i * 16);
    CP_COMMIT();
    for (int i = tid; i < 2176; i += NTHREADS)
        cpa16(sb + REG_Z + i * 16, gimg + 110592 + 34816 + i * 16);
    CP_COMMIT();

    // stage-2 epilogue (overlaps E fills): x2 hi/lo -> REG_X, vv
    {
        float vp1 = 0.0f, vp2 = 0.0f;
#pragma unroll
        for (int t = 0; t < 8; t++) {
            int c = cbase + 8 * t + 2 * q;
            float z0 = fmaxf(accA[t][0] + sBH[c],     0.0f);
            float z1 = fmaxf(accA[t][1] + sBH[c + 1], 0.0f);
            float z2 = fmaxf(accA[t][2] + sBH[c],     0.0f);
            float z3 = fmaxf(accA[t][3] + sBH[c + 1], 0.0f);
            __half h0 = __float2half_rn(z0), h1 = __float2half_rn(z1);
            __half h2 = __float2half_rn(z2), h3 = __float2half_rn(z3);
            float fl0 = z0 - __half2float(h0), fl1 = z1 - __half2float(h1);
            float fl2 = z2 - __half2float(h2), fl3 = z3 - __half2float(h3);
            float x0 = __half2float(h0) + __half2float(__float2half_rn(fl0));
            float x1 = __half2float(h1) + __half2float(__float2half_rn(fl1));
            float x2 = __half2float(h2) + __half2float(__float2half_rn(fl2));
            float x3 = __half2float(h3) + __half2float(__float2half_rn(fl3));
            vp1 = fmaf(x0, x0, vp1); vp1 = fmaf(x1, x1, vp1);
            vp2 = fmaf(x2, x2, vp2); vp2 = fmaf(x3, x3, vp2);
            u32 o1 = (u32)r1 * 272 + (u32)c * 2;
            u32 o2 = (u32)r2 * 272 + (u32)c * 2;
            *(u32*)(sc + REG_X + o1)         = pkh(__half2float(h0), __half2float(h1));
            *(u32*)(sc + REG_X + o2)         = pkh(__half2float(h2), __half2float(h3));
            *(u32*)(sc + REG_X + 17408 + o1) = pkh(fl0, fl1);
            *(u32*)(sc + REG_X + 17408 + o2) = pkh(fl2, fl3);
        }
        vp1 += __shfl_xor_sync(0xFFFFFFFFu, vp1, 1);
        vp1 += __shfl_xor_sync(0xFFFFFFFFu, vp1, 2);
        vp2 += __shfl_xor_sync(0xFFFFFFFFu, vp2, 1);
        vp2 += __shfl_xor_sync(0xFFFFFFFFu, vp2, 2);
        if (q == 0) { sVV[r1 * 2 + chalf] = vp1; sVV[r2 * 2 + chalf] = vp2; }
    }

    // ---------------- Score: 4 tiles, double-buffered Y/Z, acc ping-pong -----
    CP_WAIT(1);
    __syncthreads();                                    // E0 + x2 + vv ready
    const float vva = sVV[r1 * 2] + sVV[r1 * 2 + 1];
    const float vvb = sVV[r2 * 2] + sVV[r2 * 2 + 1];
    u32 k1[3] = {0xFFFFFFFFu, 0xFFFFFFFFu, 0xFFFFFFFFu};
    u32 k2[3] = {0xFFFFFFFFu, 0xFFFFFFFFu, 0xFFFFFFFFu};
    float accB[8][4];

#define ZERO_ACC(A)                                                           \
    do {                                                                      \
        _Pragma("unroll")                                                     \
        for (int t = 0; t < 8; t++)                                           \
            _Pragma("unroll")                                                 \
            for (int j = 0; j < 4; j++) (A)[t][j] = 0.0f;                     \
    } while (0)

#define SELECT(A, T)                                                          \
    do {                                                                      \
        int codeBase = (T) * 128 + cbase;                                     \
        _Pragma("unroll")                                                     \
        for (int t = 0; t < 8; t++) {                                         \
            int c = codeBase + 8 * t + 2 * q;                                 \
            _Pragma("unroll")                                                 \
            for (int jj = 0; jj < 2; jj++) {                                  \
                int code = c + jj;                                            \
                float ee = sEE[code];                                         \
                float da = fmaf(-2.0f, (A)[t][jj],     vva) + ee;             \
                float db = fmaf(-2.0f, (A)[t][2 + jj], vvb) + ee;             \
                key3((__float_as_uint(da) & 0xFFFFFE00u) | (u32)code, k1);    \
                key3((__float_as_uint(db) & 0xFFFFFE00u) | (u32)code, k2);    \
            }                                                                 \
        }                                                                     \
    } while (0)

    ZERO_ACC(accA);
    run_gemm_hi(sb + REG_X, sb + REG_Y, 272, 272, lane, wrow, cbase, accA);
    __syncthreads();                                    // Y reads done
    for (int i = tid; i < 2176; i += NTHREADS)          // E2 -> Y
        cpa16(sb + REG_Y + i * 16, gimg + 110592 + 2 * 34816 + i * 16);
    CP_COMMIT();
    CP_WAIT(1);                                         // E1 ready
    __syncthreads();
    ZERO_ACC(accB);
    run_gemm_hi(sb + REG_X, sb + REG_Z, 272, 272, lane, wrow, cbase, accB);
    SELECT(accA, 0);
    __syncthreads();                                    // Z reads done
    for (int i = tid; i < 2176; i += NTHREADS)          // E3 -> Z
        cpa16(sb + REG_Z + i * 16, gimg + 110592 + 3 * 34816 + i * 16);
    CP_COMMIT();
    CP_WAIT(1);                                         // E2 ready
    __syncthreads();
    ZERO_ACC(accA);
    run_gemm_hi(sb + REG_X, sb + REG_Y, 272, 272, lane, wrow, cbase, accA);
    SELECT(accB, 1);
    CP_WAIT(0);                                         // E3 ready
    __syncthreads();
    ZERO_ACC(accB);
    run_gemm_hi(sb + REG_X, sb + REG_Z, 272, 272, lane, wrow, cbase, accB);
    SELECT(accA, 2);
    SELECT(accB, 3);

    // merge top-3 across the 4 q lanes of each row half
#pragma unroll
    for (int mk = 1; mk <= 2; mk <<= 1) {
#pragma unroll
        for (int k = 0; k < 3; k++) {
            u32 o1 = __shfl_xor_sync(0xFFFFFFFFu, k1[k], mk);
            u32 o2 = __shfl_xor_sync(0xFFFFFFFFu, k2[k], mk);
            key3(o1, k1);
            key3(o2, k2);
        }
    }
    if (q == 0) {
#pragma unroll
        for (int k = 0; k < 3; k++) {
            sKEY[r1 * 6 + chalf * 3 + k] = k1[k];
            sKEY[r2 * 6 + chalf * 3 + k] = k2[k];
        }
    }
    __syncthreads();

    // -------- per-row candidates + exact fp32 re-check (4 threads/row) -------
    {
        int row = tid >> 2;       // 256 threads -> 64 rows
        int sub = tid & 3;
        u32 kk[6];
#pragma unroll
        for (int j = 0; j < 6; j++) kk[j] = sKEY[row * 6 + j];
        u32 kmin = kk[0];
#pragma unroll
        for (int j = 1; j < 6; j++) kmin = umin(kmin, kk[j]);
        float thr = __uint_as_float(kmin & 0xFFFFFE00u) + MARGIN;

        int cidx[6]; int cnt = 0;
#pragma unroll
        for (int j = 0; j < 6; j++) {
            if (__uint_as_float(kk[j] & 0xFFFFFE00u) <= thr) {
                int c = (int)(kk[j] & 511u);
                bool dup = false;
                for (int p = 0; p < cnt; p++) dup |= (cidx[p] == c);
                if (!dup) cidx[cnt++] = c;
            }
        }

        int bestI;
        if (cnt == 1) {
            bestI = cidx[0];
        } else {
            float dots[6];
#pragma unroll
            for (int j = 0; j < 6; j++) dots[j] = 0.0f;
            for (int i = 0; i < 16; i++) {
                int w = sub * 16 + i;
                u32 hw = *(const u32*)(sc + REG_X + (u32)row * 272 + (u32)w * 4);
                u32 lw = *(const u32*)(sc + REG_X + 17408 + (u32)row * 272 + (u32)w * 4);
                __half2 hh = *reinterpret_cast<__half2*>(&hw);
                __half2 ll = *reinterpret_cast<__half2*>(&lw);
                float x0 = __half2float(hh.x) + __half2float(ll.x);
                float x1 = __half2float(hh.y) + __half2float(ll.y);
                for (int j = 0; j < cnt; j++) {
                    const float* ep = emb + (size_t)cidx[j] * H_DIM + 2 * w;
                    dots[j] = fmaf(x0, __ldg(ep),     dots[j]);
                    dots[j] = fmaf(x1, __ldg(ep + 1), dots[j]);
                }
            }
            for (int j = 0; j < cnt; j++) {
                dots[j] += __shfl_xor_sync(0xFFFFFFFFu, dots[j], 1);
                dots[j] += __shfl_xor_sync(0xFFFFFFFFu, dots[j], 2);
            }
            float bestD = __int_as_float(0x7f800000);
            bestI = 0x7fffffff;
            for (int j = 0; j < cnt; j++) {
                float dd = __fsub_rn(sEE[cidx[j]], __fmul_rn(2.0f, dots[j]));
                if (dd < bestD || (dd == bestD && cidx[j] < bestI)) { bestD = dd; bestI = cidx[j]; }
            }
        }

        if (sub == 0) {
            int gr = rowBase + row;
            float4 p0 = *(const float4*)(g_probs + bestI * A_DIM);
            float4 p1 = *(const float4*)(g_probs + bestI * A_DIM + 4);
            float4* po = (float4*)out;
            po[gr * 2 + 0] = p0;
            po[gr * 2 + 1] = p1;
            out[(size_t)N_ROWS * A_DIM + gr] = g_value[bestI];
        }
    }
}

// ===================== launch =====================
extern "C" void kernel_launch(void* const* d_in, const int* in_sizes, int n_in,
                              void* d_out, int out_size)
{
    const float* inputs = (const float*)d_in[0];
    const float* W1  = (const float*)d_in[1];
    const float* b1  = (const float*)d_in[2];
    const float* Wh  = (const float*)d_in[3];
    const float* bh  = (const float*)d_in[4];
    const float* emb = (const float*)d_in[5];
    const float* Wa  = (const float*)d_in[6];
    const float* ba  = (const float*)d_in[7];
    const float* Wv  = (const float*)d_in[8];
    const float* bv  = (const float*)d_in[9];

    cudaFuncSetAttribute(fused_kernel,
                         cudaFuncAttributeMaxDynamicSharedMemorySize, SMEM_BYTES);

    prep_all<<<416, 256>>>(emb, Wa, ba, Wv, bv, W1, Wh);
    fused_kernel<<<N_ROWS / TM, NTHREADS, SMEM_BYTES>>>(
        inputs, b1, bh, emb, (float*)d_out);
}